// round 1
// baseline (speedup 1.0000x reference)
#include <cuda_runtime.h>

// ---------------------------------------------------------------------------
// SpatialAttn2: B=16, L=32, N=256, P=16, H=4, F=12, HID=4, W=16
// Output tuple flattened: out[B,W,F,N] | attn1[B,W,H,N,N] | attn2[B,W,N,N]
//                         | Wv1[H,P,HID] | Wv2[P,F]
// ---------------------------------------------------------------------------

#define N_   256
#define P_   16
#define H_   4
#define F_   12
#define HID_ 4
#define W_   16
#define L_   32
#define BW_  256

static const unsigned long long OFF_A1  = 786432ull;              // out size
static const unsigned long long OFF_A2  = 786432ull + 67108864ull;
static const unsigned long long OFF_WV1 = 786432ull + 67108864ull + 16777216ull;
static const unsigned long long OFF_WV2 = OFF_WV1 + 256ull;
static const long long TOT_FULL = 84672960ll;

__device__ unsigned int g_maskbits[N_ * 8];

// ---------------------------------------------------------------------------
// prologue: pack adjacency mask into bitmask + passthrough weight copies
// ---------------------------------------------------------------------------
__global__ void pack_mask_kernel(const int* __restrict__ mask,
                                 const float* __restrict__ Wv1,
                                 const float* __restrict__ Wv2,
                                 float* __restrict__ out, int wW) {
    int t = blockIdx.x * 256 + threadIdx.x;   // 8 blocks x 256 = 2048 words
    int row  = t >> 3;
    int word = t & 7;
    const int* mr = mask + row * N_ + word * 32;
    unsigned int v = 0u;
#pragma unroll
    for (int b = 0; b < 32; b++) v |= (mr[b] > 0 ? (1u << b) : 0u);
    g_maskbits[t] = v;
    if (wW && blockIdx.x == 0) {
        out[OFF_WV1 + threadIdx.x] = Wv1[threadIdx.x];               // 256
        if (threadIdx.x < 192) out[OFF_WV2 + threadIdx.x] = Wv2[threadIdx.x];
    }
}

// ---------------------------------------------------------------------------
struct __align__(16) Smem {
    float xT [P_][N_];       // x transposed: xT[p][n]
    float h1T[P_][N_];       // layer-1 output transposed
    float Qs [N_][20];       // query rows, padded to 20 floats (16B-aligned rows)
    float VT [F_][N_];       // value rows transposed (layer1 uses 4, layer2 12)
    unsigned int mb[N_][8];  // mask bitmask
    float Wa1[H_][P_][P_];
    float Wv1[H_][P_][HID_];
    float Wa2[P_][P_];
    float Wv2[P_][F_];
};

__device__ __forceinline__ float warp_max(float v) {
#pragma unroll
    for (int o = 16; o > 0; o >>= 1) v = fmaxf(v, __shfl_xor_sync(0xffffffffu, v, o));
    return v;
}
__device__ __forceinline__ float warp_sum(float v) {
#pragma unroll
    for (int o = 16; o > 0; o >>= 1) v += __shfl_xor_sync(0xffffffffu, v, o);
    return v;
}

__global__ void __launch_bounds__(256, 1)
spatial_attn_kernel(const float* __restrict__ inp,
                    const float* __restrict__ Wa1,
                    const float* __restrict__ Wv1,
                    const float* __restrict__ Wa2,
                    const float* __restrict__ Wv2,
                    float* __restrict__ out, int wA) {
    extern __shared__ char smraw[];
    Smem& S = *reinterpret_cast<Smem*>(smraw);
    const int tid  = threadIdx.x;
    const int lane = tid & 31;
    const int wid  = tid >> 5;
    const int bw   = blockIdx.x;
    const int b    = bw >> 4;
    const int w    = bw & 15;

    // ---- stage 0: load xT, mask bits, weights --------------------------------
#pragma unroll
    for (int p = 0; p < P_; p++)
        S.xT[p][tid] = inp[(b * L_ + w + p) * N_ + tid];
#pragma unroll
    for (int k = 0; k < 8; k++)
        (&S.mb[0][0])[tid + 256 * k] = g_maskbits[tid + 256 * k];
#pragma unroll
    for (int k = 0; k < 4; k++)
        (&S.Wa1[0][0][0])[tid + 256 * k] = Wa1[tid + 256 * k];
    (&S.Wv1[0][0][0])[tid] = Wv1[tid];
    (&S.Wa2[0][0])[tid]    = Wa2[tid];
    if (tid < 192) (&S.Wv2[0][0])[tid] = Wv2[tid];
    __syncthreads();

    float* a1 = out + OFF_A1 + (unsigned long long)bw * (H_ * N_ * N_);
    float* a2 = out + OFF_A2 + (unsigned long long)bw * (N_ * N_);

    // =========================== layer 1 (4 heads) ===========================
#pragma unroll 1
    for (int h = 0; h < H_; h++) {
        // stage 1: Q = 0.25 * X @ Wa1[h] ; VT = (X @ Wv1[h])^T
        {
            float q[P_], v[HID_];
#pragma unroll
            for (int j = 0; j < P_; j++) q[j] = 0.f;
#pragma unroll
            for (int o = 0; o < HID_; o++) v[o] = 0.f;
#pragma unroll
            for (int i = 0; i < P_; i++) {
                float xi = S.xT[i][tid];
#pragma unroll
                for (int j = 0; j < P_; j++) q[j] += xi * S.Wa1[h][i][j];
#pragma unroll
                for (int o = 0; o < HID_; o++) v[o] += xi * S.Wv1[h][i][o];
            }
#pragma unroll
            for (int j4 = 0; j4 < 4; j4++) {
                float4 t4 = make_float4(q[j4*4+0]*0.25f, q[j4*4+1]*0.25f,
                                        q[j4*4+2]*0.25f, q[j4*4+3]*0.25f);
                *reinterpret_cast<float4*>(&S.Qs[tid][j4*4]) = t4;
            }
#pragma unroll
            for (int o = 0; o < HID_; o++) S.VT[o][tid] = v[o];
        }
        __syncthreads();

        float* a1h = a1 + h * N_ * N_;
        // stage 2: warp-cooperative rows, 4 rows per group, lane owns 4 columns
#pragma unroll 1
        for (int rg = 0; rg < 8; rg++) {
            const int row0 = (wid << 5) + (rg << 2);
            float q[4][P_];
#pragma unroll
            for (int r = 0; r < 4; r++)
#pragma unroll
                for (int j4 = 0; j4 < 4; j4++) {
                    float4 t4 = *reinterpret_cast<const float4*>(&S.Qs[row0 + r][j4*4]);
                    q[r][j4*4+0] = t4.x; q[r][j4*4+1] = t4.y;
                    q[r][j4*4+2] = t4.z; q[r][j4*4+3] = t4.w;
                }
            float e[4][8];
            float mx[4] = {-1e30f, -1e30f, -1e30f, -1e30f};
#pragma unroll
            for (int c = 0; c < 2; c++) {
                const int m0 = c * 128 + (lane << 2);
                float4 s4[4];
#pragma unroll
                for (int r = 0; r < 4; r++) s4[r] = make_float4(0.f, 0.f, 0.f, 0.f);
#pragma unroll
                for (int i = 0; i < P_; i++) {
                    float4 xv = *reinterpret_cast<const float4*>(&S.xT[i][m0]);
#pragma unroll
                    for (int r = 0; r < 4; r++) {
                        s4[r].x += q[r][i] * xv.x;
                        s4[r].y += q[r][i] * xv.y;
                        s4[r].z += q[r][i] * xv.z;
                        s4[r].w += q[r][i] * xv.w;
                    }
                }
#pragma unroll
                for (int r = 0; r < 4; r++) {
                    unsigned int mw   = S.mb[row0 + r][c * 4 + (lane >> 3)];
                    unsigned int bits = mw >> ((lane & 7) << 2);
                    float sx = (bits & 1u) ? s4[r].x : -1e30f;
                    float sy = (bits & 2u) ? s4[r].y : -1e30f;
                    float sz = (bits & 4u) ? s4[r].z : -1e30f;
                    float sw = (bits & 8u) ? s4[r].w : -1e30f;
                    e[r][c*4+0] = sx; e[r][c*4+1] = sy;
                    e[r][c*4+2] = sz; e[r][c*4+3] = sw;
                    mx[r] = fmaxf(mx[r], fmaxf(fmaxf(sx, sy), fmaxf(sz, sw)));
                }
            }
            float inv[4];
#pragma unroll
            for (int r = 0; r < 4; r++) {
                float m_ = warp_max(mx[r]);
                float sm = 0.f;
#pragma unroll
                for (int k = 0; k < 8; k++) {
                    float ee = __expf(e[r][k] - m_);
                    e[r][k] = ee;
                    sm += ee;
                }
                sm = warp_sum(sm);
                inv[r] = __frcp_rn(sm);
            }
            float acc[4][HID_];
#pragma unroll
            for (int r = 0; r < 4; r++)
#pragma unroll
                for (int o = 0; o < HID_; o++) acc[r][o] = 0.f;
#pragma unroll
            for (int c = 0; c < 2; c++) {
                const int m0 = c * 128 + (lane << 2);
                float4 en[4];
#pragma unroll
                for (int r = 0; r < 4; r++) {
                    en[r].x = e[r][c*4+0] * inv[r];
                    en[r].y = e[r][c*4+1] * inv[r];
                    en[r].z = e[r][c*4+2] * inv[r];
                    en[r].w = e[r][c*4+3] * inv[r];
                    if (wA)
                        *reinterpret_cast<float4*>(&a1h[(row0 + r) * N_ + m0]) = en[r];
                }
#pragma unroll
                for (int o = 0; o < HID_; o++) {
                    float4 vv = *reinterpret_cast<const float4*>(&S.VT[o][m0]);
#pragma unroll
                    for (int r = 0; r < 4; r++)
                        acc[r][o] += en[r].x * vv.x + en[r].y * vv.y
                                   + en[r].z * vv.z + en[r].w * vv.w;
                }
            }
#pragma unroll
            for (int r = 0; r < 4; r++) {
#pragma unroll
                for (int o = 0; o < HID_; o++) acc[r][o] = warp_sum(acc[r][o]);
                if (lane == 0) {
#pragma unroll
                    for (int o = 0; o < HID_; o++)
                        S.h1T[h * HID_ + o][row0 + r] = acc[r][o];
                }
            }
        }
        __syncthreads();
    }

    // ================================ layer 2 ================================
    {
        float q[P_], v[F_];
#pragma unroll
        for (int j = 0; j < P_; j++) q[j] = 0.f;
#pragma unroll
        for (int o = 0; o < F_; o++) v[o] = 0.f;
#pragma unroll
        for (int i = 0; i < P_; i++) {
            float xi = S.h1T[i][tid];
#pragma unroll
            for (int j = 0; j < P_; j++) q[j] += xi * S.Wa2[i][j];
#pragma unroll
            for (int o = 0; o < F_; o++) v[o] += xi * S.Wv2[i][o];
        }
        // safe to overwrite Qs/VT: last head ended with __syncthreads()
#pragma unroll
        for (int j4 = 0; j4 < 4; j4++) {
            float4 t4 = make_float4(q[j4*4+0]*0.25f, q[j4*4+1]*0.25f,
                                    q[j4*4+2]*0.25f, q[j4*4+3]*0.25f);
            *reinterpret_cast<float4*>(&S.Qs[tid][j4*4]) = t4;
        }
#pragma unroll
        for (int o = 0; o < F_; o++) S.VT[o][tid] = v[o];
    }
    __syncthreads();

#pragma unroll 1
    for (int rg = 0; rg < 16; rg++) {
        const int row0 = (wid << 5) + (rg << 1);
        float q[2][P_];
#pragma unroll
        for (int r = 0; r < 2; r++)
#pragma unroll
            for (int j4 = 0; j4 < 4; j4++) {
                float4 t4 = *reinterpret_cast<const float4*>(&S.Qs[row0 + r][j4*4]);
                q[r][j4*4+0] = t4.x; q[r][j4*4+1] = t4.y;
                q[r][j4*4+2] = t4.z; q[r][j4*4+3] = t4.w;
            }
        float e[2][8];
        float mx[2] = {-1e30f, -1e30f};
#pragma unroll
        for (int c = 0; c < 2; c++) {
            const int m0 = c * 128 + (lane << 2);
            float4 s4[2];
#pragma unroll
            for (int r = 0; r < 2; r++) s4[r] = make_float4(0.f, 0.f, 0.f, 0.f);
#pragma unroll
            for (int i = 0; i < P_; i++) {
                float4 xv = *reinterpret_cast<const float4*>(&S.h1T[i][m0]);
#pragma unroll
                for (int r = 0; r < 2; r++) {
                    s4[r].x += q[r][i] * xv.x;
                    s4[r].y += q[r][i] * xv.y;
                    s4[r].z += q[r][i] * xv.z;
                    s4[r].w += q[r][i] * xv.w;
                }
            }
#pragma unroll
            for (int r = 0; r < 2; r++) {
                unsigned int mw   = S.mb[row0 + r][c * 4 + (lane >> 3)];
                unsigned int bits = mw >> ((lane & 7) << 2);
                float sx = (bits & 1u) ? s4[r].x : -1e30f;
                float sy = (bits & 2u) ? s4[r].y : -1e30f;
                float sz = (bits & 4u) ? s4[r].z : -1e30f;
                float sw = (bits & 8u) ? s4[r].w : -1e30f;
                e[r][c*4+0] = sx; e[r][c*4+1] = sy;
                e[r][c*4+2] = sz; e[r][c*4+3] = sw;
                mx[r] = fmaxf(mx[r], fmaxf(fmaxf(sx, sy), fmaxf(sz, sw)));
            }
        }
        float inv[2];
#pragma unroll
        for (int r = 0; r < 2; r++) {
            float m_ = warp_max(mx[r]);
            float sm = 0.f;
#pragma unroll
            for (int k = 0; k < 8; k++) {
                float ee = __expf(e[r][k] - m_);
                e[r][k] = ee;
                sm += ee;
            }
            sm = warp_sum(sm);
            inv[r] = __frcp_rn(sm);
        }
        float acc[2][F_];
#pragma unroll
        for (int r = 0; r < 2; r++)
#pragma unroll
            for (int o = 0; o < F_; o++) acc[r][o] = 0.f;
#pragma unroll
        for (int c = 0; c < 2; c++) {
            const int m0 = c * 128 + (lane << 2);
            float4 en[2];
#pragma unroll
            for (int r = 0; r < 2; r++) {
                en[r].x = e[r][c*4+0] * inv[r];
                en[r].y = e[r][c*4+1] * inv[r];
                en[r].z = e[r][c*4+2] * inv[r];
                en[r].w = e[r][c*4+3] * inv[r];
                if (wA)
                    *reinterpret_cast<float4*>(&a2[(row0 + r) * N_ + m0]) = en[r];
            }
#pragma unroll
            for (int o = 0; o < F_; o++) {
                float4 vv = *reinterpret_cast<const float4*>(&S.VT[o][m0]);
#pragma unroll
                for (int r = 0; r < 2; r++)
                    acc[r][o] += en[r].x * vv.x + en[r].y * vv.y
                               + en[r].z * vv.z + en[r].w * vv.w;
            }
        }
#pragma unroll
        for (int r = 0; r < 2; r++) {
#pragma unroll
            for (int o = 0; o < F_; o++) acc[r][o] = warp_sum(acc[r][o]);
            if (lane == 0) {
#pragma unroll
                for (int f = 0; f < F_; f++)
                    out[((unsigned long long)bw * F_ + f) * N_ + row0 + r] = acc[r][f];
            }
        }
    }
}

// ---------------------------------------------------------------------------
extern "C" void kernel_launch(void* const* d_in, const int* in_sizes, int n_in,
                              void* d_out, int out_size) {
    const float* inp  = (const float*)d_in[0];
    const int*   mask = (const int*)  d_in[1];
    const float* Wa1  = (const float*)d_in[2];
    const float* Wv1  = (const float*)d_in[3];
    const float* Wa2  = (const float*)d_in[4];
    const float* Wv2  = (const float*)d_in[5];
    float* out = (float*)d_out;

    // Adapt to harness output contract: write attn maps / weight copies only
    // when the output buffer actually contains them.
    const int wA = (out_size >= (int)(OFF_A2 + (unsigned long long)BW_ * N_ * N_)) ? 1 : 0;
    const int wW = (out_size >= (int)TOT_FULL) ? 1 : 0;

    cudaFuncSetAttribute(spatial_attn_kernel,
                         cudaFuncAttributeMaxDynamicSharedMemorySize,
                         (int)sizeof(Smem));

    pack_mask_kernel<<<8, 256>>>(mask, Wv1, Wv2, out, wW);
    spatial_attn_kernel<<<BW_, 256, sizeof(Smem)>>>(inp, Wa1, Wv1, Wa2, Wv2, out, wA);
}